// round 2
// baseline (speedup 1.0000x reference)
#include <cuda_runtime.h>
#include <cuda_bf16.h>

#define BB 64
#define TT 512
#define DD 1024
#define CH 128               // float columns per chunk
#define NCHUNK (DD / CH)     // 8
#define NTHREADS 256
#define COLS (CH / 4)        // 32 float4 column groups (one warp-width)
#define ROWS (NTHREADS / COLS) // 8 row-phases

// Scratch (allocation-free per harness rules)
__device__ float g_s[BB * DD];
__device__ float g_norm[BB];

__global__ void zero_norm_kernel() {
    if (threadIdx.x < BB) g_norm[threadIdx.x] = 0.0f;
}

__global__ __launch_bounds__(NTHREADS) void pass1_kernel(
    const float* __restrict__ vseq,     // [B,T,D]
    const int*   __restrict__ slen,     // [B]
    const int*   __restrict__ words,    // [B,T]
    const float* __restrict__ weights,  // [VOCAB]
    float*       __restrict__ out)      // [2,B,D]: y then y_hat
{
    const int b     = blockIdx.x;
    const int chunk = blockIdx.y;
    const int L     = slen[b];

    __shared__ float w_sh[TT];
    // Gather per-token weights once per block (only rows we will touch)
    for (int t = threadIdx.x; t < L; t += NTHREADS) {
        w_sh[t] = __ldg(&weights[words[b * TT + t]]);
    }
    __syncthreads();

    const int c = threadIdx.x & (COLS - 1);   // float4 column within chunk
    const int r = threadIdx.x >> 5;           // row phase 0..7 (COLS==32)

    const float4* base =
        (const float4*)(vseq + (size_t)b * TT * DD + (size_t)chunk * CH);
    const int rowstride = DD / 4;             // float4 per row

    float4 s  = make_float4(0.f, 0.f, 0.f, 0.f);
    float4 yh = make_float4(0.f, 0.f, 0.f, 0.f);

    #pragma unroll 4
    for (int t = r; t < L; t += ROWS) {
        float4 v = __ldcs(&base[(size_t)t * rowstride + c]);
        float  w = w_sh[t];                   // broadcast within warp
        s.x  += v.x;     s.y  += v.y;     s.z  += v.z;     s.w  += v.w;
        yh.x += v.x * w; yh.y += v.y * w; yh.z += v.z * w; yh.w += v.w * w;
    }

    // Cross-row-phase reduction via shared
    __shared__ float4 s_sh[ROWS][COLS];
    __shared__ float4 y_sh[ROWS][COLS];
    s_sh[r][c] = s;
    y_sh[r][c] = yh;
    __syncthreads();

    if (threadIdx.x < COLS) {
        const int cc = threadIdx.x;
        float4 S = s_sh[0][cc];
        float4 Y = y_sh[0][cc];
        #pragma unroll
        for (int rr = 1; rr < ROWS; rr++) {
            float4 a = s_sh[rr][cc];
            float4 h = y_sh[rr][cc];
            S.x += a.x; S.y += a.y; S.z += a.z; S.w += a.w;
            Y.x += h.x; Y.y += h.y; Y.z += h.z; Y.w += h.w;
        }
        const int d = chunk * CH + cc * 4;
        *(float4*)&g_s[b * DD + d] = S;
        // y_hat goes to second half of out
        *(float4*)&out[(size_t)BB * DD + (size_t)b * DD + d] = Y;

        // |s| partial norm: warp-reduce over the 32 column groups
        float a = fabsf(S.x) + fabsf(S.y) + fabsf(S.z) + fabsf(S.w);
        #pragma unroll
        for (int off = 16; off > 0; off >>= 1)
            a += __shfl_down_sync(0xffffffffu, a, off);
        if (cc == 0) atomicAdd(&g_norm[b], a);
    }
}

__global__ void pass2_kernel(float* __restrict__ out) {
    const int i = blockIdx.x * blockDim.x + threadIdx.x;  // over B*D
    if (i < BB * DD) {
        const int b = i >> 10;  // / DD
        out[i] = g_s[i] * rsqrtf(g_norm[b]);
    }
}

extern "C" void kernel_launch(void* const* d_in, const int* in_sizes, int n_in,
                              void* d_out, int out_size) {
    const float* vseq    = (const float*)d_in[0];   // [B,T,D] fp32
    const int*   slen    = (const int*)  d_in[1];   // [B] int32
    const int*   words   = (const int*)  d_in[2];   // [B,T] int32
    const float* weights = (const float*)d_in[3];   // [VOCAB] fp32
    float*       out     = (float*)d_out;           // [2*B*D] fp32: y, y_hat

    zero_norm_kernel<<<1, 64>>>();

    dim3 grid(BB, NCHUNK);
    pass1_kernel<<<grid, NTHREADS>>>(vseq, slen, words, weights, out);

    pass2_kernel<<<(BB * DD + 255) / 256, 256>>>(out);
}

// round 5
// speedup vs baseline: 1.0233x; 1.0233x over previous
#include <cuda_runtime.h>
#include <cuda_bf16.h>

#define BB 64
#define TT 512
#define DD 1024
#define CH 128               // float columns per chunk
#define NCHUNK (DD / CH)     // 8
#define NTHREADS 256
#define COLS (CH / 4)        // 32 float4 column groups (one warp-width)
#define ROWS (NTHREADS / COLS) // 8 row-phases

// Scratch (allocation-free; zero-initialized at module load, and the kernel
// restores cnt/norm to 0 before exit so every graph replay sees clean state)
__device__ float        g_s[BB * DD];
__device__ float        g_norm[BB];
__device__ unsigned int g_cnt[BB];

__global__ __launch_bounds__(NTHREADS) void fused_kernel(
    const float* __restrict__ vseq,     // [B,T,D]
    const int*   __restrict__ slen,     // [B]
    const int*   __restrict__ words,    // [B,T]
    const float* __restrict__ weights,  // [VOCAB]
    float*       __restrict__ out)      // [2,B,D]: y then y_hat
{
    const int b     = blockIdx.x;
    const int chunk = blockIdx.y;
    const int L     = slen[b];

    __shared__ float w_sh[TT];
    for (int t = threadIdx.x; t < L; t += NTHREADS) {
        w_sh[t] = __ldg(&weights[words[b * TT + t]]);
    }
    __syncthreads();

    const int c = threadIdx.x & (COLS - 1);   // float4 column within chunk
    const int r = threadIdx.x >> 5;           // row phase 0..7

    const float4* base =
        (const float4*)(vseq + (size_t)b * TT * DD + (size_t)chunk * CH);
    const int rowstride = DD / 4;

    float4 s  = make_float4(0.f, 0.f, 0.f, 0.f);
    float4 yh = make_float4(0.f, 0.f, 0.f, 0.f);

    #pragma unroll 4
    for (int t = r; t < L; t += ROWS) {
        float4 v = __ldcs(&base[(size_t)t * rowstride + c]);
        float  w = w_sh[t];
        s.x  += v.x;     s.y  += v.y;     s.z  += v.z;     s.w  += v.w;
        yh.x += v.x * w; yh.y += v.y * w; yh.z += v.z * w; yh.w += v.w * w;
    }

    // Cross-row-phase reduction via shared
    __shared__ float4 s_sh[ROWS][COLS];
    __shared__ float4 y_sh[ROWS][COLS];
    s_sh[r][c] = s;
    y_sh[r][c] = yh;
    __syncthreads();

    if (threadIdx.x < COLS) {
        const int cc = threadIdx.x;
        float4 S = s_sh[0][cc];
        float4 Y = y_sh[0][cc];
        #pragma unroll
        for (int rr = 1; rr < ROWS; rr++) {
            float4 a = s_sh[rr][cc];
            float4 h = y_sh[rr][cc];
            S.x += a.x; S.y += a.y; S.z += a.z; S.w += a.w;
            Y.x += h.x; Y.y += h.y; Y.z += h.z; Y.w += h.w;
        }
        const int d = chunk * CH + cc * 4;
        *(float4*)&g_s[b * DD + d] = S;
        *(float4*)&out[(size_t)BB * DD + (size_t)b * DD + d] = Y;

        float a = fabsf(S.x) + fabsf(S.y) + fabsf(S.z) + fabsf(S.w);
        #pragma unroll
        for (int off = 16; off > 0; off >>= 1)
            a += __shfl_down_sync(0xffffffffu, a, off);
        if (cc == 0) atomicAdd(&g_norm[b], a);
    }

    // Publish this chunk's results, then let the LAST chunk-block of this
    // batch perform the normalization epilogue.
    __threadfence();
    __syncthreads();

    __shared__ int isLast;
    if (threadIdx.x == 0) {
        unsigned int arrived = atomicAdd(&g_cnt[b], 1u);
        isLast = (arrived == NCHUNK - 1) ? 1 : 0;
    }
    __syncthreads();

    if (isLast) {
        const float nrm  = __ldcg(&g_norm[b]);  // L2 (atomics live in L2)
        const float rinv = rsqrtf(nrm);
        const float4* sp = (const float4*)&g_s[b * DD];
        float4* yp = (float4*)&out[(size_t)b * DD];
        for (int i = threadIdx.x; i < DD / 4; i += NTHREADS) {
            float4 S = __ldcg(&sp[i]);          // bypass L1 (cross-SM data)
            S.x *= rinv; S.y *= rinv; S.z *= rinv; S.w *= rinv;
            yp[i] = S;
        }
        if (threadIdx.x == 0) {                 // restore state for replay
            g_cnt[b]  = 0u;
            g_norm[b] = 0.0f;
        }
    }
}

extern "C" void kernel_launch(void* const* d_in, const int* in_sizes, int n_in,
                              void* d_out, int out_size) {
    const float* vseq    = (const float*)d_in[0];   // [B,T,D] fp32
    const int*   slen    = (const int*)  d_in[1];   // [B] int32
    const int*   words   = (const int*)  d_in[2];   // [B,T] int32
    const float* weights = (const float*)d_in[3];   // [VOCAB] fp32
    float*       out     = (float*)d_out;           // [2*B*D] fp32: y, y_hat

    dim3 grid(BB, NCHUNK);
    fused_kernel<<<grid, NTHREADS>>>(vseq, slen, words, weights, out);
}